// round 9
// baseline (speedup 1.0000x reference)
#include <cuda_runtime.h>
#include <math.h>

// Problem constants
#define NB   64      // batch N
#define TT   1024    // time steps
#define DD   512     // input dim
#define HHD  512     // hidden dim
#define FH   2048    // 4*H

// ---------------- device scratch (allocation-free rule: __device__ globals) ----
__device__ __align__(16) float g_xw[NB * TT * FH];   // 512 MB: xW+b, layout (t, n, col)
__device__ __align__(16) float g_WhT[FH * HHD];      // Wh transposed: (2048, 512)
__device__ __align__(16) float g_h[2][NB * HHD];     // double-buffered hidden state
__device__ unsigned g_count;                         // grid barrier counter

// ---------------- init: reset barrier counter + load h0 -----------------------
__global__ void init_kernel(const float* __restrict__ h0) {
    int i = blockIdx.x * blockDim.x + threadIdx.x;
    if (i == 0) g_count = 0u;
    if (i < NB * HHD) g_h[0][i] = h0[i];
}

// ---------------- transpose Wh (512,2048) -> WhT (2048,512) -------------------
__global__ void transpose_wh(const float* __restrict__ Wh) {
    int idx = blockIdx.x * blockDim.x + threadIdx.x;   // < 512*2048, coalesced read
    int k = idx >> 11;
    int col = idx & 2047;
    g_WhT[col * HHD + k] = Wh[idx];
}

// ---------------- phase 1: xW = X @ Wx + b  (65536x2048x512 SGEMM) ------------
// 128x128 tile, BK=8, 256 threads, 8x8 micro-tile. Output written in (t,n,col)
// layout so the recurrence reads one contiguous 512KB slab per step.
__global__ __launch_bounds__(256, 2)
void gemm_xw(const float* __restrict__ X, const float* __restrict__ Wx,
             const float* __restrict__ bias) {
    __shared__ __align__(16) float As[8][128];
    __shared__ __align__(16) float Bs[8][128];

    const int tid  = threadIdx.x;
    const int row0 = blockIdx.y * 128;
    const int col0 = blockIdx.x * 128;

    const int aRow = tid >> 1;            // 0..127
    const int aCol = (tid & 1) * 4;       // 0 or 4
    const int bRow = tid >> 5;            // 0..7
    const int bCol = (tid & 31) * 4;      // 0..124

    const int tx = tid & 15;              // col group
    const int ty = tid >> 4;              // row group (0..15)

    const float* Ap = X  + (size_t)(row0 + aRow) * DD + aCol;
    const float* Bp = Wx + (size_t)bRow * FH + col0 + bCol;

    float acc[8][8];
#pragma unroll
    for (int i = 0; i < 8; i++)
#pragma unroll
        for (int jq = 0; jq < 8; jq++) acc[i][jq] = 0.f;

    for (int k0 = 0; k0 < DD; k0 += 8) {
        float4 av = __ldg((const float4*)(Ap + k0));
        float4 bv = __ldg((const float4*)(Bp + (size_t)k0 * FH));
        As[aCol + 0][aRow] = av.x;
        As[aCol + 1][aRow] = av.y;
        As[aCol + 2][aRow] = av.z;
        As[aCol + 3][aRow] = av.w;
        *(float4*)&Bs[bRow][bCol] = bv;
        __syncthreads();
#pragma unroll
        for (int k = 0; k < 8; k++) {
            float4 a0 = *(const float4*)&As[k][ty * 8];
            float4 a1 = *(const float4*)&As[k][ty * 8 + 4];
            float4 b0 = *(const float4*)&Bs[k][tx * 4];
            float4 b1 = *(const float4*)&Bs[k][64 + tx * 4];
            float ar[8] = {a0.x, a0.y, a0.z, a0.w, a1.x, a1.y, a1.z, a1.w};
            float br[8] = {b0.x, b0.y, b0.z, b0.w, b1.x, b1.y, b1.z, b1.w};
#pragma unroll
            for (int i = 0; i < 8; i++)
#pragma unroll
                for (int jq = 0; jq < 8; jq++)
                    acc[i][jq] = fmaf(ar[i], br[jq], acc[i][jq]);
        }
        __syncthreads();
    }

    float4 bb0 = __ldg((const float4*)&bias[col0 + tx * 4]);
    float4 bb1 = __ldg((const float4*)&bias[col0 + 64 + tx * 4]);
#pragma unroll
    for (int i = 0; i < 8; i++) {
        int m  = row0 + ty * 8 + i;
        int tt = m & (TT - 1);
        int nn = m >> 10;
        float* orow = g_xw + ((size_t)(tt * NB + nn)) * FH + col0;
        float4 v0 = make_float4(acc[i][0] + bb0.x, acc[i][1] + bb0.y,
                                acc[i][2] + bb0.z, acc[i][3] + bb0.w);
        float4 v1 = make_float4(acc[i][4] + bb1.x, acc[i][5] + bb1.y,
                                acc[i][6] + bb1.z, acc[i][7] + bb1.w);
        *(float4*)(orow + tx * 4)      = v0;
        *(float4*)(orow + 64 + tx * 4) = v1;
    }
}

// ---------------- phase 2: persistent LSTM recurrence -------------------------
// 128 CTAs x 256 threads. CTA b owns gate-local columns j0=b*4 .. j0+3 for all
// 4 gates and all 64 batch rows. Thread (n = tid>>2, jj = tid&3) owns output
// element (n, j0+jj): its cell state c lives in a register for all 1024 steps.
// Per step: a[g] = xw[t][n][g*512+j] + sum_k h[n][k] * WhT[g*512+j][k].
// h double-buffered in global; readers use ld.global.cg (L2) for coherence.
#define KK  64
#define NCH (HHD / KK)   // 8 k-chunks per step

__global__ __launch_bounds__(256, 1)
void lstm_kernel(float* __restrict__ out) {
    __shared__ __align__(16) float sh_h[2][64][68];   // [buf][n][kk], pad 4
    __shared__ __align__(16) float sh_w[2][16][68];   // [buf][g*4+jj][kk]

    const int tid = threadIdx.x;
    const int nl  = tid >> 2;          // batch row 0..63
    const int jj  = tid & 3;           // column within CTA's 4
    const int j0  = blockIdx.x * 4;
    const int j   = j0 + jj;           // gate-local column 0..511

    // W-tile loader mapping: smem row wc encodes (g = wc>>2, jw = wc&3)
    const int wc   = tid >> 4;                 // 0..15
    const int wrow = (wc >> 2) * HHD + j0 + (wc & 3);  // WhT row (a-column)
    const int wkq  = (tid & 15) * 4;           // 0..60

    float c = 0.f;
    int nb = 0;

    for (int t = 0; t < TT; t++) {
        const float* __restrict__ hread = g_h[nb];

        // prefetch this thread's 4 xW values (DRAM; consumed ~8k cycles later)
        const size_t xb = ((size_t)(t * NB + nl)) * FH + j;
        float xw0 = __ldg(&g_xw[xb]);
        float xw1 = __ldg(&g_xw[xb + 512]);
        float xw2 = __ldg(&g_xw[xb + 1024]);
        float xw3 = __ldg(&g_xw[xb + 1536]);

        float acc0 = 0.f, acc1 = 0.f, acc2 = 0.f, acc3 = 0.f;

        // prefetch k-chunk 0 into registers
        float4 hr[4];
        float4 wr;
#pragma unroll
        for (int i = 0; i < 4; i++)
            hr[i] = __ldcg((const float4*)&hread[nl * HHD + i * 16 + jj * 4]);
        wr = __ldg((const float4*)&g_WhT[(size_t)wrow * HHD + wkq]);

        int buf = 0;
#pragma unroll
        for (int ch = 0; ch < NCH; ch++) {
            // stage registers -> smem
#pragma unroll
            for (int i = 0; i < 4; i++)
                *(float4*)&sh_h[buf][nl][i * 16 + jj * 4] = hr[i];
            *(float4*)&sh_w[buf][wc][wkq] = wr;
            __syncthreads();

            // prefetch next chunk (latency overlapped with compute below)
            if (ch + 1 < NCH) {
                const int k0 = (ch + 1) * KK;
#pragma unroll
                for (int i = 0; i < 4; i++)
                    hr[i] = __ldcg((const float4*)
                                   &hread[nl * HHD + k0 + i * 16 + jj * 4]);
                wr = __ldg((const float4*)&g_WhT[(size_t)wrow * HHD + k0 + wkq]);
            }

            // compute: 16 FMA per 4 k, 4 gate accumulators
#pragma unroll
            for (int kk = 0; kk < KK; kk += 4) {
                float4 h4 = *(const float4*)&sh_h[buf][nl][kk];
                float4 wA = *(const float4*)&sh_w[buf][0 + jj][kk];
                float4 wB = *(const float4*)&sh_w[buf][4 + jj][kk];
                float4 wC = *(const float4*)&sh_w[buf][8 + jj][kk];
                float4 wD = *(const float4*)&sh_w[buf][12 + jj][kk];
                acc0 = fmaf(h4.x, wA.x, acc0); acc0 = fmaf(h4.y, wA.y, acc0);
                acc0 = fmaf(h4.z, wA.z, acc0); acc0 = fmaf(h4.w, wA.w, acc0);
                acc1 = fmaf(h4.x, wB.x, acc1); acc1 = fmaf(h4.y, wB.y, acc1);
                acc1 = fmaf(h4.z, wB.z, acc1); acc1 = fmaf(h4.w, wB.w, acc1);
                acc2 = fmaf(h4.x, wC.x, acc2); acc2 = fmaf(h4.y, wC.y, acc2);
                acc2 = fmaf(h4.z, wC.z, acc2); acc2 = fmaf(h4.w, wC.w, acc2);
                acc3 = fmaf(h4.x, wD.x, acc3); acc3 = fmaf(h4.y, wD.y, acc3);
                acc3 = fmaf(h4.z, wD.z, acc3); acc3 = fmaf(h4.w, wD.w, acc3);
            }
            buf ^= 1;
        }

        // gates: split order [i, f, o, g]
        float ai = xw0 + acc0;
        float af = xw1 + acc1;
        float ao = xw2 + acc2;
        float ag = xw3 + acc3;
        float ig = 1.f / (1.f + expf(-ai));
        float fg = 1.f / (1.f + expf(-af));
        float og = 1.f / (1.f + expf(-ao));
        float gg = tanhf(ag);
        c = fg * c + ig * gg;
        float hn = og * tanhf(c);

        out[((size_t)nl * TT + t) * HHD + j] = hn;
        g_h[nb ^ 1][nl * HHD + j] = hn;

        // ---- global barrier: release(store->fence) + RED arrive + ld.cg spin
        __threadfence();
        __syncthreads();
        if (tid == 0) {
            atomicAdd(&g_count, 1u);   // result unused -> RED (no return path)
            unsigned tgt = (unsigned)(t + 1) * (unsigned)gridDim.x;
            unsigned v;
            do {
                asm volatile("ld.global.cg.u32 %0, [%1];"
                             : "=r"(v) : "l"(&g_count) : "memory");
                if (v >= tgt) break;
                __nanosleep(64);
            } while (true);
        }
        __syncthreads();
        __threadfence();   // acquire side
        nb ^= 1;
    }
}

// ---------------- launch ------------------------------------------------------
extern "C" void kernel_launch(void* const* d_in, const int* in_sizes, int n_in,
                              void* d_out, int out_size) {
    (void)in_sizes; (void)n_in; (void)out_size;
    const float* x  = (const float*)d_in[0];   // (64,1024,512)
    const float* h0 = (const float*)d_in[1];   // (64,512)
    const float* Wx = (const float*)d_in[2];   // (512,2048)
    const float* Wh = (const float*)d_in[3];   // (512,2048)
    const float* b  = (const float*)d_in[4];   // (2048)
    float* out = (float*)d_out;                // (64,1024,512) fp32

    init_kernel<<<128, 256>>>(h0);                       // reset barrier + h
    transpose_wh<<<(DD * FH) / 256, 256>>>(Wh);          // WhT
    gemm_xw<<<dim3(FH / 128, (NB * TT) / 128), 256>>>(x, Wx, b);  // phase 1
    lstm_kernel<<<128, 256>>>(out);                      // phase 2 (persistent)
}

// round 11
// speedup vs baseline: 1.1150x; 1.1150x over previous
#include <cuda_runtime.h>
#include <math.h>

// Problem constants
#define NB   64      // batch N
#define TT   1024    // time steps
#define DD   512     // input dim
#define HHD  512     // hidden dim
#define FH   2048    // 4*H

// ---------------- device scratch (allocation-free rule: __device__ globals) ----
__device__ __align__(16) float g_xw[NB * TT * FH];   // xW+b, layout (t, n, col)
__device__ __align__(16) float g_WhT[FH * HHD];      // Wh transposed: (2048, 512)
__device__ __align__(16) float g_h[2][NB * HHD];     // double-buffered hidden state
__device__ unsigned g_count;                         // grid barrier counter

// packed fp32x2 FMA (sm_100+): d = a*b + d elementwise on a register pair.
__device__ __forceinline__ void ffma2(unsigned long long& d,
                                      unsigned long long a,
                                      unsigned long long b) {
    asm("fma.rn.f32x2 %0, %1, %2, %0;" : "+l"(d) : "l"(a), "l"(b));
}

// ---------------- init: reset barrier counter + load h0 -----------------------
__global__ void init_kernel(const float* __restrict__ h0) {
    int i = blockIdx.x * blockDim.x + threadIdx.x;
    if (i == 0) g_count = 0u;
    if (i < NB * HHD) g_h[0][i] = h0[i];
}

// ---------------- transpose Wh (512,2048) -> WhT (2048,512) -------------------
__global__ void transpose_wh(const float* __restrict__ Wh) {
    int idx = blockIdx.x * blockDim.x + threadIdx.x;   // coalesced read
    int k = idx >> 11;
    int col = idx & 2047;
    g_WhT[col * HHD + k] = Wh[idx];
}

// ---------------- phase 1: xW = X @ Wx + b  (65536x2048x512 SGEMM) ------------
// (unchanged from R9 — proven correct)
__global__ __launch_bounds__(256, 2)
void gemm_xw(const float* __restrict__ X, const float* __restrict__ Wx,
             const float* __restrict__ bias) {
    __shared__ __align__(16) float As[8][128];
    __shared__ __align__(16) float Bs[8][128];

    const int tid  = threadIdx.x;
    const int row0 = blockIdx.y * 128;
    const int col0 = blockIdx.x * 128;

    const int aRow = tid >> 1;
    const int aCol = (tid & 1) * 4;
    const int bRow = tid >> 5;
    const int bCol = (tid & 31) * 4;

    const int tx = tid & 15;
    const int ty = tid >> 4;

    const float* Ap = X  + (size_t)(row0 + aRow) * DD + aCol;
    const float* Bp = Wx + (size_t)bRow * FH + col0 + bCol;

    float acc[8][8];
#pragma unroll
    for (int i = 0; i < 8; i++)
#pragma unroll
        for (int jq = 0; jq < 8; jq++) acc[i][jq] = 0.f;

    for (int k0 = 0; k0 < DD; k0 += 8) {
        float4 av = __ldg((const float4*)(Ap + k0));
        float4 bv = __ldg((const float4*)(Bp + (size_t)k0 * FH));
        As[aCol + 0][aRow] = av.x;
        As[aCol + 1][aRow] = av.y;
        As[aCol + 2][aRow] = av.z;
        As[aCol + 3][aRow] = av.w;
        *(float4*)&Bs[bRow][bCol] = bv;
        __syncthreads();
#pragma unroll
        for (int k = 0; k < 8; k++) {
            float4 a0 = *(const float4*)&As[k][ty * 8];
            float4 a1 = *(const float4*)&As[k][ty * 8 + 4];
            float4 b0 = *(const float4*)&Bs[k][tx * 4];
            float4 b1 = *(const float4*)&Bs[k][64 + tx * 4];
            float ar[8] = {a0.x, a0.y, a0.z, a0.w, a1.x, a1.y, a1.z, a1.w};
            float br[8] = {b0.x, b0.y, b0.z, b0.w, b1.x, b1.y, b1.z, b1.w};
#pragma unroll
            for (int i = 0; i < 8; i++)
#pragma unroll
                for (int jq = 0; jq < 8; jq++)
                    acc[i][jq] = fmaf(ar[i], br[jq], acc[i][jq]);
        }
        __syncthreads();
    }

    float4 bb0 = __ldg((const float4*)&bias[col0 + tx * 4]);
    float4 bb1 = __ldg((const float4*)&bias[col0 + 64 + tx * 4]);
#pragma unroll
    for (int i = 0; i < 8; i++) {
        int m  = row0 + ty * 8 + i;
        int tt = m & (TT - 1);
        int nn = m >> 10;
        float* orow = g_xw + ((size_t)(tt * NB + nn)) * FH + col0;
        float4 v0 = make_float4(acc[i][0] + bb0.x, acc[i][1] + bb0.y,
                                acc[i][2] + bb0.z, acc[i][3] + bb0.w);
        float4 v1 = make_float4(acc[i][4] + bb1.x, acc[i][5] + bb1.y,
                                acc[i][6] + bb1.z, acc[i][7] + bb1.w);
        *(float4*)(orow + tx * 4)      = v0;
        *(float4*)(orow + 64 + tx * 4) = v1;
    }
}

// ---------------- phase 2: persistent LSTM recurrence -------------------------
// 128 CTAs x 256 threads. CTA b owns gate-local columns j0..j0+3 across all 4
// gates. Thread (nl = tid>>2, jj = tid&3) owns element (nl, j0+jj): all 4 gate
// accumulators, cell state c in a register for all 1024 steps (R9's proven
// ownership/activation mapping — no shuffles, no gate splitting).
// New vs R9: Wh slice (16 rows x 512) staged to smem ONCE before the t-loop;
// full h (64x512) staged to smem once per step (coalesced ld.cg, one sync);
// inner dot products use packed fma.rn.f32x2 (half the FMA issue slots).
#define HSTRIDE 516                               // 512 + 4 pad
#define LSTM_SMEM_FLOATS ((NB + 16) * HSTRIDE)    // h tile + W tile
#define LSTM_SMEM_BYTES  (LSTM_SMEM_FLOATS * 4)   // 165,120 B

__global__ __launch_bounds__(256, 1)
void lstm_kernel(float* __restrict__ out) {
    extern __shared__ float sm[];
    float* sh = sm;                    // h tile [64][516]
    float* sw = sm + NB * HSTRIDE;     // W tile [16][516], row r = gate*4 + col

    const int tid = threadIdx.x;
    const int nl  = tid >> 2;          // batch row 0..63
    const int jj  = tid & 3;           // column within CTA's 4
    const int j0  = blockIdx.x * 4;
    const int j   = j0 + jj;           // gate-local column 0..511

    // ---- stage Wh slice once: smem row r <-> (gate = r>>2, col = r&3) ----
    for (int i = tid; i < 2048; i += 256) {        // 16 rows x 128 float4
        int r  = i >> 7;
        int kq = (i & 127) * 4;
        int G  = (r >> 2) * HHD + j0 + (r & 3);    // WhT row (a-column)
        float4 v = __ldg((const float4*)&g_WhT[(size_t)G * HHD + kq]);
        *(float4*)&sw[r * HSTRIDE + kq] = v;
    }

    // per-thread pointers (ulonglong2 = 4 floats = 2 packed f32x2)
    const ulonglong2* hq = (const ulonglong2*)(sh + nl * HSTRIDE);
    const ulonglong2* w0 = (const ulonglong2*)(sw + (0 * 4 + jj) * HSTRIDE);
    const ulonglong2* w1 = (const ulonglong2*)(sw + (1 * 4 + jj) * HSTRIDE);
    const ulonglong2* w2 = (const ulonglong2*)(sw + (2 * 4 + jj) * HSTRIDE);
    const ulonglong2* w3 = (const ulonglong2*)(sw + (3 * 4 + jj) * HSTRIDE);

    float c = 0.f;
    int nb = 0;

    for (int t = 0; t < TT; t++) {
        // xW prefetch (streaming; consumed at step end) — identical to R9
        const size_t xb = ((size_t)(t * NB + nl)) * FH + j;
        float xw0 = __ldg(&g_xw[xb]);
        float xw1 = __ldg(&g_xw[xb + 512]);
        float xw2 = __ldg(&g_xw[xb + 1024]);
        float xw3 = __ldg(&g_xw[xb + 1536]);

        // ---- stage full h into smem (coalesced ld.cg, high MLP) ----
        const float* hsrc = g_h[nb];
#pragma unroll
        for (int u = 0; u < 32; u++) {
            int i = tid + u * 256;                    // float4 index 0..8191
            float4 v = __ldcg((const float4*)&hsrc[i * 4]);
            *(float4*)&sh[(i >> 7) * HSTRIDE + (i & 127) * 4] = v;
        }
        __syncthreads();

        // ---- 512-k dot products: 5 LDS.128 + 8 FFMA2 per 4k, no syncs ----
        unsigned long long a0 = 0ull, a1 = 0ull, a2 = 0ull, a3 = 0ull;
#pragma unroll 8
        for (int kq = 0; kq < HHD / 4; kq++) {
            ulonglong2 hv = hq[kq];
            ulonglong2 v0 = w0[kq];
            ulonglong2 v1 = w1[kq];
            ulonglong2 v2 = w2[kq];
            ulonglong2 v3 = w3[kq];
            ffma2(a0, hv.x, v0.x); ffma2(a0, hv.y, v0.y);
            ffma2(a1, hv.x, v1.x); ffma2(a1, hv.y, v1.y);
            ffma2(a2, hv.x, v2.x); ffma2(a2, hv.y, v2.y);
            ffma2(a3, hv.x, v3.x); ffma2(a3, hv.y, v3.y);
        }
        union { unsigned long long u; float2 f; } u0, u1, u2, u3;
        u0.u = a0; u1.u = a1; u2.u = a2; u3.u = a3;

        // gates (split order [i, f, o, g]) — identical math to R9
        float ai = xw0 + u0.f.x + u0.f.y;
        float af = xw1 + u1.f.x + u1.f.y;
        float ao = xw2 + u2.f.x + u2.f.y;
        float ag = xw3 + u3.f.x + u3.f.y;
        float ig = 1.f / (1.f + expf(-ai));
        float fg = 1.f / (1.f + expf(-af));
        float og = 1.f / (1.f + expf(-ao));
        float gg = tanhf(ag);
        c = fg * c + ig * gg;
        float hn = og * tanhf(c);

        out[((size_t)nl * TT + t) * HHD + j] = hn;
        g_h[nb ^ 1][nl * HHD + j] = hn;

        // ---- global barrier: release fence + RED arrive + ld.cg spin ----
        __threadfence();
        __syncthreads();
        if (tid == 0) {
            atomicAdd(&g_count, 1u);
            unsigned tgt = (unsigned)(t + 1) * (unsigned)gridDim.x;
            unsigned v;
            do {
                asm volatile("ld.global.cg.u32 %0, [%1];"
                             : "=r"(v) : "l"(&g_count) : "memory");
                if (v >= tgt) break;
                __nanosleep(64);
            } while (true);
        }
        __syncthreads();
        __threadfence();   // acquire side
        nb ^= 1;
    }
}

// ---------------- launch ------------------------------------------------------
extern "C" void kernel_launch(void* const* d_in, const int* in_sizes, int n_in,
                              void* d_out, int out_size) {
    (void)in_sizes; (void)n_in; (void)out_size;
    const float* x  = (const float*)d_in[0];   // (64,1024,512)
    const float* h0 = (const float*)d_in[1];   // (64,512)
    const float* Wx = (const float*)d_in[2];   // (512,2048)
    const float* Wh = (const float*)d_in[3];   // (512,2048)
    const float* b  = (const float*)d_in[4];   // (2048)
    float* out = (float*)d_out;                // (64,1024,512) fp32

    cudaFuncSetAttribute(lstm_kernel,
                         cudaFuncAttributeMaxDynamicSharedMemorySize,
                         LSTM_SMEM_BYTES);

    init_kernel<<<128, 256>>>(h0);
    transpose_wh<<<(DD * FH) / 256, 256>>>(Wh);
    gemm_xw<<<dim3(FH / 128, (NB * TT) / 128), 256>>>(x, Wx, b);
    lstm_kernel<<<128, 256, LSTM_SMEM_BYTES>>>(out);
}

// round 12
// speedup vs baseline: 1.1218x; 1.0061x over previous
#include <cuda_runtime.h>
#include <math.h>

// Problem constants
#define NB   64      // batch N
#define TT   1024    // time steps
#define DD   512     // input dim
#define HHD  512     // hidden dim
#define FH   2048    // 4*H

// ---------------- device scratch (allocation-free rule: __device__ globals) ----
__device__ __align__(16) float g_xw[NB * TT * FH];   // xW+b, layout (t, n, col)
__device__ __align__(16) float g_WhT[FH * HHD];      // Wh transposed: (2048, 512)
__device__ __align__(16) float g_h[2][NB * HHD];     // double-buffered hidden state
__device__ unsigned g_count;                         // grid barrier counter

// packed fp32x2 ops (sm_100+)
__device__ __forceinline__ void ffma2(unsigned long long& d,
                                      unsigned long long a,
                                      unsigned long long b) {
    asm("fma.rn.f32x2 %0, %1, %2, %0;" : "+l"(d) : "l"(a), "l"(b));
}
__device__ __forceinline__ void fadd2(unsigned long long& d,
                                      unsigned long long a) {
    asm("add.rn.f32x2 %0, %0, %1;" : "+l"(d) : "l"(a));
}
__device__ __forceinline__ unsigned long long pack2(float x) {
    unsigned long long r;
    asm("mov.b64 %0, {%1, %1};" : "=l"(r) : "f"(x));
    return r;
}

// ---------------- init: reset barrier counter + load h0 -----------------------
__global__ void init_kernel(const float* __restrict__ h0) {
    int i = blockIdx.x * blockDim.x + threadIdx.x;
    if (i == 0) g_count = 0u;
    if (i < NB * HHD) g_h[0][i] = h0[i];
}

// ---------------- transpose Wh (512,2048) -> WhT (2048,512) -------------------
__global__ void transpose_wh(const float* __restrict__ Wh) {
    int idx = blockIdx.x * blockDim.x + threadIdx.x;   // coalesced read
    int k = idx >> 11;
    int col = idx & 2047;
    g_WhT[col * HHD + k] = Wh[idx];
}

// ---------------- phase 1: xW = X @ Wx + b  (65536x2048x512 SGEMM) ------------
// 128x128 tile, BK=8, 256 threads, 8x8 micro-tile with packed f32x2 FMAs:
// per k: 4 LDS.128 + 8 packs + 32 FFMA2 (was 64 FFMA).
__global__ __launch_bounds__(256, 2)
void gemm_xw(const float* __restrict__ X, const float* __restrict__ Wx,
             const float* __restrict__ bias) {
    __shared__ __align__(16) float As[8][128];
    __shared__ __align__(16) float Bs[8][128];

    const int tid  = threadIdx.x;
    const int row0 = blockIdx.y * 128;
    const int col0 = blockIdx.x * 128;

    const int aRow = tid >> 1;
    const int aCol = (tid & 1) * 4;
    const int bRow = tid >> 5;
    const int bCol = (tid & 31) * 4;

    const int tx = tid & 15;
    const int ty = tid >> 4;

    const float* Ap = X  + (size_t)(row0 + aRow) * DD + aCol;
    const float* Bp = Wx + (size_t)bRow * FH + col0 + bCol;

    // acc2[i][p]: packed pair p of row i. p=0,1 -> cols tx*4..+3 ; p=2,3 -> +64
    unsigned long long acc2[8][4];
#pragma unroll
    for (int i = 0; i < 8; i++)
#pragma unroll
        for (int p = 0; p < 4; p++) acc2[i][p] = 0ull;

    for (int k0 = 0; k0 < DD; k0 += 8) {
        float4 av = __ldg((const float4*)(Ap + k0));
        float4 bv = __ldg((const float4*)(Bp + (size_t)k0 * FH));
        As[aCol + 0][aRow] = av.x;
        As[aCol + 1][aRow] = av.y;
        As[aCol + 2][aRow] = av.z;
        As[aCol + 3][aRow] = av.w;
        *(float4*)&Bs[bRow][bCol] = bv;
        __syncthreads();
#pragma unroll
        for (int k = 0; k < 8; k++) {
            float4 a0 = *(const float4*)&As[k][ty * 8];
            float4 a1 = *(const float4*)&As[k][ty * 8 + 4];
            ulonglong2 bp0 = *(const ulonglong2*)&Bs[k][tx * 4];       // pairs 0,1
            ulonglong2 bp1 = *(const ulonglong2*)&Bs[k][64 + tx * 4];  // pairs 2,3
            float ar[8] = {a0.x, a0.y, a0.z, a0.w, a1.x, a1.y, a1.z, a1.w};
#pragma unroll
            for (int i = 0; i < 8; i++) {
                unsigned long long aa = pack2(ar[i]);
                ffma2(acc2[i][0], aa, bp0.x);
                ffma2(acc2[i][1], aa, bp0.y);
                ffma2(acc2[i][2], aa, bp1.x);
                ffma2(acc2[i][3], aa, bp1.y);
            }
        }
        __syncthreads();
    }

    float4 bb0 = __ldg((const float4*)&bias[col0 + tx * 4]);
    float4 bb1 = __ldg((const float4*)&bias[col0 + 64 + tx * 4]);
#pragma unroll
    for (int i = 0; i < 8; i++) {
        int m  = row0 + ty * 8 + i;
        int tt = m & (TT - 1);
        int nn = m >> 10;
        float* orow = g_xw + ((size_t)(tt * NB + nn)) * FH + col0;
        union { unsigned long long u; float2 f; } p0, p1, p2, p3;
        p0.u = acc2[i][0]; p1.u = acc2[i][1];
        p2.u = acc2[i][2]; p3.u = acc2[i][3];
        float4 v0 = make_float4(p0.f.x + bb0.x, p0.f.y + bb0.y,
                                p1.f.x + bb0.z, p1.f.y + bb0.w);
        float4 v1 = make_float4(p2.f.x + bb1.x, p2.f.y + bb1.y,
                                p3.f.x + bb1.z, p3.f.y + bb1.w);
        *(float4*)(orow + tx * 4)      = v0;
        *(float4*)(orow + 64 + tx * 4) = v1;
    }
}

// ---------------- phase 2: persistent LSTM recurrence -------------------------
// 128 CTAs x 512 threads (16 warps/SM for latency hiding). Same ownership as
// R11: CTA b owns gate-local columns j0..j0+3; logical thread (nl = (tid>>2)&63,
// jj = tid&3) owns element (nl, j0+jj). NEW: z = tid>>8 splits the k-range in
// half; z=1 writes its 4 packed partial sums to smem, z=0 combines (f32x2 add),
// runs the R11-identical activation path, and owns c.
#define HSTRIDE 516                               // 512 + 4 pad
#define HTILE   (NB * HSTRIDE)                    // 33024 floats
#define WTILE   (16 * HSTRIDE)                    // 8256 floats
#define REDF    2048                              // 8KB reduction buffer (floats)
#define LSTM_SMEM_FLOATS (HTILE + WTILE + REDF)
#define LSTM_SMEM_BYTES  (LSTM_SMEM_FLOATS * 4)   // 173,312 B

__global__ __launch_bounds__(512, 1)
void lstm_kernel(float* __restrict__ out) {
    extern __shared__ float sm[];
    float* sh = sm;                         // h tile [64][516]
    float* sw = sm + HTILE;                 // W tile [16][516], row = gate*4+col
    unsigned long long* red = (unsigned long long*)(sm + HTILE + WTILE);

    const int tid = threadIdx.x;
    const int z   = tid >> 8;          // k-half
    const int nl  = (tid >> 2) & 63;   // batch row
    const int jj  = tid & 3;           // column within CTA's 4
    const int j0  = blockIdx.x * 4;
    const int j   = j0 + jj;

    // ---- stage Wh slice once: smem row r <-> (gate = r>>2, col = r&3) ----
    for (int i = tid; i < 2048; i += 512) {        // 16 rows x 128 float4
        int r  = i >> 7;
        int kq = (i & 127) * 4;
        int G  = (r >> 2) * HHD + j0 + (r & 3);    // WhT row (a-column)
        float4 v = __ldg((const float4*)&g_WhT[(size_t)G * HHD + kq]);
        *(float4*)&sw[r * HSTRIDE + kq] = v;
    }

    // per-thread pointers (ulonglong2 = 4 floats); offset into own k-half
    const ulonglong2* hq = (const ulonglong2*)(sh + nl * HSTRIDE) + z * 64;
    const ulonglong2* w0 = (const ulonglong2*)(sw + (0 * 4 + jj) * HSTRIDE) + z * 64;
    const ulonglong2* w1 = (const ulonglong2*)(sw + (1 * 4 + jj) * HSTRIDE) + z * 64;
    const ulonglong2* w2 = (const ulonglong2*)(sw + (2 * 4 + jj) * HSTRIDE) + z * 64;
    const ulonglong2* w3 = (const ulonglong2*)(sw + (3 * 4 + jj) * HSTRIDE) + z * 64;

    float c = 0.f;
    int nb = 0;

    for (int t = 0; t < TT; t++) {
        // xW prefetch (only the activation half needs it)
        float xw0 = 0.f, xw1 = 0.f, xw2 = 0.f, xw3 = 0.f;
        if (z == 0) {
            const size_t xb = ((size_t)(t * NB + nl)) * FH + j;
            xw0 = __ldg(&g_xw[xb]);
            xw1 = __ldg(&g_xw[xb + 512]);
            xw2 = __ldg(&g_xw[xb + 1024]);
            xw3 = __ldg(&g_xw[xb + 1536]);
        }

        // ---- stage full h into smem (coalesced ld.cg, high MLP) ----
        const float* hsrc = g_h[nb];
#pragma unroll
        for (int u = 0; u < 16; u++) {
            int i = tid + u * 512;                    // float4 index 0..8191
            float4 v = __ldcg((const float4*)&hsrc[i * 4]);
            *(float4*)&sh[(i >> 7) * HSTRIDE + (i & 127) * 4] = v;
        }
        __syncthreads();

        // ---- half-k dot products: 5 LDS.128 + 8 FFMA2 per 4k, 64 iters ----
        unsigned long long a0 = 0ull, a1 = 0ull, a2 = 0ull, a3 = 0ull;
#pragma unroll 4
        for (int kq = 0; kq < 64; kq++) {
            ulonglong2 hv = hq[kq];
            ulonglong2 v0 = w0[kq];
            ulonglong2 v1 = w1[kq];
            ulonglong2 v2 = w2[kq];
            ulonglong2 v3 = w3[kq];
            ffma2(a0, hv.x, v0.x); ffma2(a0, hv.y, v0.y);
            ffma2(a1, hv.x, v1.x); ffma2(a1, hv.y, v1.y);
            ffma2(a2, hv.x, v2.x); ffma2(a2, hv.y, v2.y);
            ffma2(a3, hv.x, v3.x); ffma2(a3, hv.y, v3.y);
        }

        // ---- cross-half reduction (disjoint 8KB smem region) ----
        if (z == 1) {
            unsigned long long* r4 = red + (tid & 255) * 4;
            r4[0] = a0; r4[1] = a1; r4[2] = a2; r4[3] = a3;
        }
        __syncthreads();

        if (z == 0) {
            const unsigned long long* r4 = red + tid * 4;
            fadd2(a0, r4[0]); fadd2(a1, r4[1]);
            fadd2(a2, r4[2]); fadd2(a3, r4[3]);

            union { unsigned long long u; float2 f; } u0, u1, u2, u3;
            u0.u = a0; u1.u = a1; u2.u = a2; u3.u = a3;

            // gates (split order [i, f, o, g]) — identical math to R11
            float ai = xw0 + u0.f.x + u0.f.y;
            float af = xw1 + u1.f.x + u1.f.y;
            float ao = xw2 + u2.f.x + u2.f.y;
            float ag = xw3 + u3.f.x + u3.f.y;
            float ig = 1.f / (1.f + expf(-ai));
            float fg = 1.f / (1.f + expf(-af));
            float og = 1.f / (1.f + expf(-ao));
            float gg = tanhf(ag);
            c = fg * c + ig * gg;
            float hn = og * tanhf(c);

            out[((size_t)nl * TT + t) * HHD + j] = hn;
            g_h[nb ^ 1][nl * HHD + j] = hn;
        }

        // ---- global barrier: release fence + RED arrive + ld.cg spin ----
        __threadfence();
        __syncthreads();
        if (tid == 0) {
            atomicAdd(&g_count, 1u);
            unsigned tgt = (unsigned)(t + 1) * (unsigned)gridDim.x;
            unsigned v;
            do {
                asm volatile("ld.global.cg.u32 %0, [%1];"
                             : "=r"(v) : "l"(&g_count) : "memory");
                if (v >= tgt) break;
                __nanosleep(64);
            } while (true);
        }
        __syncthreads();
        __threadfence();   // acquire side
        nb ^= 1;
    }
}

// ---------------- launch ------------------------------------------------------
extern "C" void kernel_launch(void* const* d_in, const int* in_sizes, int n_in,
                              void* d_out, int out_size) {
    (void)in_sizes; (void)n_in; (void)out_size;
    const float* x  = (const float*)d_in[0];   // (64,1024,512)
    const float* h0 = (const float*)d_in[1];   // (64,512)
    const float* Wx = (const float*)d_in[2];   // (512,2048)
    const float* Wh = (const float*)d_in[3];   // (512,2048)
    const float* b  = (const float*)d_in[4];   // (2048)
    float* out = (float*)d_out;                // (64,1024,512) fp32

    cudaFuncSetAttribute(lstm_kernel,
                         cudaFuncAttributeMaxDynamicSharedMemorySize,
                         LSTM_SMEM_BYTES);

    init_kernel<<<128, 256>>>(h0);
    transpose_wh<<<(DD * FH) / 256, 256>>>(Wh);
    gemm_xw<<<dim3(FH / 128, (NB * TT) / 128), 256>>>(x, Wx, b);
    lstm_kernel<<<128, 512, LSTM_SMEM_BYTES>>>(out);
}